// round 15
// baseline (speedup 1.0000x reference)
#include <cuda_runtime.h>

// packed-f32x2 helpers (ptxas never auto-fuses; PTX-only path)
#define PACK2B(p, t)      asm("mov.b64 %0, {%1,%1};" : "=l"(p) : "f"(t))
#define PACK2(p, a, b)    asm("mov.b64 %0, {%1,%2};" : "=l"(p) : "f"(a), "f"(b))
#define UNPACK2(lo, hi, p) asm("mov.b64 {%0,%1}, %2;" : "=f"(lo), "=f"(hi) : "l"(p))
#define FFMA2(acc, a, b)  asm("fma.rn.f32x2 %0, %1, %2, %0;" : "+l"(acc) : "l"(a), "l"(b))
typedef unsigned long long u64;

// ---------------- scratch (__device__ globals; no allocation allowed) ----------------
__device__ float g_hx[8*32*256];
__device__ float g_hy[8*32*256];
__device__ float g_hz[8*32*256];
__device__ float g_attraw[8*2*32768];        // pre-softmax logits [b][h][x][y][z]
__device__ float g_partmax[8*2*32];          // per (b,h,x) block max
__device__ float g_partsum[8*2*32];          // per (b,h,x) Σexp(v - localmax)
__device__ float g_part[8*32*256];           // per (b,x) logits partials

// ---------------- K1: projections (R13-identical) ----------------
__global__ void __launch_bounds__(256) k_proj(
    const float* __restrict__ xin, const float* __restrict__ yin, const float* __restrict__ zin,
    const float* __restrict__ Vx, const float* __restrict__ gx, const float* __restrict__ bx,
    const float* __restrict__ Vy, const float* __restrict__ gy, const float* __restrict__ by,
    const float* __restrict__ Vz, const float* __restrict__ gz, const float* __restrict__ bz) {
    __shared__ float sIn[32*128];
    __shared__ float sV[64*33];
    __shared__ float red[256];
    int q = blockIdx.x, b = blockIdx.y, m = blockIdx.z;
    const float* in   = (m == 0) ? xin : (m == 1) ? yin : zin;
    const float* V    = (m == 0) ? Vx  : (m == 1) ? Vy  : Vz;
    const float* gp   = (m == 0) ? gx  : (m == 1) ? gy  : gz;
    const float* bias = (m == 0) ? bx  : (m == 1) ? by  : bz;
    float* out        = (m == 0) ? g_hx : (m == 1) ? g_hy : g_hz;
    int tid = threadIdx.x;
    int k0 = q * 64;

    for (int e = tid; e < 4096; e += 256) sIn[e] = in[b * 4096 + e];
    const float4* V4 = (const float4*)V;
    float ss = 0.f;
    #pragma unroll 8
    for (int i = tid; i < 8192; i += 256) {
        float4 v = V4[i];
        ss += v.x*v.x + v.y*v.y + v.z*v.z + v.w*v.w;
    }

    int kk = tid & 63, rg = tid >> 6, r0 = rg * 8;
    float acc[8] = {0,0,0,0,0,0,0,0};
    for (int dc = 0; dc < 128; dc += 32) {
        __syncthreads();
        for (int e = tid; e < 2048; e += 256) {
            int kr = e >> 5, d = e & 31;
            sV[kr * 33 + d] = V[(k0 + kr) * 128 + dc + d];
        }
        __syncthreads();
        for (int d = 0; d < 32; d += 4) {
            float v0 = sV[kk*33 + d],     v1 = sV[kk*33 + d + 1];
            float v2 = sV[kk*33 + d + 2], v3 = sV[kk*33 + d + 3];
            #pragma unroll
            for (int r = 0; r < 8; r++) {
                float4 iv = *(const float4*)&sIn[(r0 + r) * 128 + dc + d];
                acc[r] += iv.x * v0 + iv.y * v1 + iv.z * v2 + iv.w * v3;
            }
        }
    }
    __syncthreads();
    red[tid] = ss; __syncthreads();
    for (int s = 128; s > 0; s >>= 1) {
        if (tid < s) red[tid] += red[tid + s];
        __syncthreads();
    }
    float scale = gp[0] / sqrtf(red[0]);
    float bb = bias[k0 + kk];
    #pragma unroll
    for (int r = 0; r < 8; r++) {
        float v = acc[r] * scale + bb;
        out[(b * 32 + r0 + r) * 256 + k0 + kk] = v > 0.f ? v : 0.f;
    }
}

// ---------------- K2: att GEMM, inner loop on packed f32x2 ----------------
__global__ void __launch_bounds__(128) k_att(const float* __restrict__ Vh,
                                             const float* __restrict__ ghp,
                                             const float* __restrict__ bhp) {
    __shared__ float st[32*64];
    __shared__ float sw[64*68];
    __shared__ float red[128];
    int x = blockIdx.x, b = blockIdx.y;
    int tid = threadIdx.x;
    int yg = tid >> 4, zg = tid & 15;

    float ssh = 0.f;
    for (int i = tid; i < 512; i += 128) { float v = Vh[i]; ssh += v * v; }
    red[tid] = ssh; __syncthreads();
    for (int s = 64; s > 0; s >>= 1) { if (tid < s) red[tid] += red[tid + s]; __syncthreads(); }
    float scaleH = ghp[0] / sqrtf(red[0]);

    u64 a01[4] = {0,0,0,0}, a23[4] = {0,0,0,0};   // (zh0,zh1) and (zh2,zh3) per y
    const float* hx  = g_hx + (b * 32 + x) * 256;
    const float* hyB = g_hy + b * 8192;
    const float* hzB = g_hz + b * 8192;
    for (int c = 0; c < 4; c++) {
        int k0 = c * 64;
        __syncthreads();
        for (int e = tid; e < 2048; e += 128) {
            int kc = e & 63, y = e >> 6;
            st[y * 64 + kc] = hx[k0 + kc] * hyB[y * 256 + k0 + kc];
        }
        for (int e = tid; e < 4096; e += 128) {
            int kc = e & 63, zh = e >> 6;
            sw[kc * 68 + zh] = hzB[(zh >> 1) * 256 + k0 + kc] *
                               Vh[(zh & 1) * 256 + k0 + kc] * scaleH;
        }
        __syncthreads();
        #pragma unroll 4
        for (int kc = 0; kc < 64; kc++) {
            // sw row: byte offset 4*(kc*68 + zg*4) — 16B aligned (272·kc + 16·zg)
            const u64* w64 = (const u64*)&sw[kc * 68 + zg * 4];
            u64 w01 = w64[0], w23 = w64[1];
            #pragma unroll
            for (int i = 0; i < 4; i++) {
                float t = st[(yg*4 + i) * 64 + kc];
                u64 tp; PACK2B(tp, t);
                FFMA2(a01[i], tp, w01);
                FFMA2(a23[i], tp, w23);
            }
        }
    }
    // unpack to the R13 float4 accumulator layout
    float4 acc[4];
    #pragma unroll
    for (int i = 0; i < 4; i++) {
        UNPACK2(acc[i].x, acc[i].y, a01[i]);
        UNPACK2(acc[i].z, acc[i].w, a23[i]);
    }
    float b0 = bhp[0], b1 = bhp[1];
    float m0 = -1e30f, m1 = -1e30f;
    float* r0base = g_attraw + ((b * 2 + 0) * 32 + x) * 1024;
    float* r1base = g_attraw + ((b * 2 + 1) * 32 + x) * 1024;
    int z0 = zg * 2;
    #pragma unroll
    for (int i = 0; i < 4; i++) {
        int y = yg * 4 + i;
        float4 v = acc[i];
        v.x += b0; v.y += b1; v.z += b0; v.w += b1;
        m0 = fmaxf(m0, fmaxf(v.x, v.z));
        m1 = fmaxf(m1, fmaxf(v.y, v.w));
        r0base[y * 32 + z0]     = v.x;
        r1base[y * 32 + z0]     = v.y;
        r0base[y * 32 + z0 + 1] = v.z;
        r1base[y * 32 + z0 + 1] = v.w;
    }
    __syncthreads();
    red[tid] = m0; __syncthreads();
    for (int s = 64; s > 0; s >>= 1) { if (tid < s) red[tid] = fmaxf(red[tid], red[tid + s]); __syncthreads(); }
    float M0 = red[0]; __syncthreads();
    red[tid] = m1; __syncthreads();
    for (int s = 64; s > 0; s >>= 1) { if (tid < s) red[tid] = fmaxf(red[tid], red[tid + s]); __syncthreads(); }
    float M1 = red[0]; __syncthreads();
    float s0 = 0.f, s1 = 0.f;
    #pragma unroll
    for (int i = 0; i < 4; i++) {
        float4 v = acc[i];
        s0 += expf(v.x + b0 - M0) + expf(v.z + b0 - M0);
        s1 += expf(v.y + b1 - M1) + expf(v.w + b1 - M1);
    }
    red[tid] = s0; __syncthreads();
    for (int s = 64; s > 0; s >>= 1) { if (tid < s) red[tid] += red[tid + s]; __syncthreads(); }
    float S0 = red[0]; __syncthreads();
    red[tid] = s1; __syncthreads();
    for (int s = 64; s > 0; s >>= 1) { if (tid < s) red[tid] += red[tid + s]; __syncthreads(); }
    if (tid == 0) {
        g_partmax[(b * 2 + 0) * 32 + x] = M0;
        g_partmax[(b * 2 + 1) * 32 + x] = M1;
        g_partsum[(b * 2 + 0) * 32 + x] = S0;
        g_partsum[(b * 2 + 1) * 32 + x] = red[0];
    }
}

// ---------------- K3: softmax-finalize + att_out + logit partials (packed f32x2 z-loop) ----------------
__global__ void __launch_bounds__(256) k_fuse(float* __restrict__ att_out) {
    __shared__ float sa[1024];
    __shared__ float shzN[8192];   // [z][k], natural
    __shared__ float sstat[4];
    int x = blockIdx.x, b = blockIdx.y, tid = threadIdx.x;

    const float* hzB = g_hz + b * 8192;
    {
        float4* s4 = (float4*)shzN;
        const float4* g4 = (const float4*)hzB;
        for (int e = tid; e < 2048; e += 256) s4[e] = g4[e];
    }
    if (tid < 64) {
        int h = tid >> 5, lane = tid & 31;
        float m = g_partmax[(b * 2 + h) * 32 + lane];
        float s = g_partsum[(b * 2 + h) * 32 + lane];
        float M = m;
        #pragma unroll
        for (int o = 16; o > 0; o >>= 1) M = fmaxf(M, __shfl_xor_sync(0xffffffffu, M, o));
        float se = s * expf(m - M);
        #pragma unroll
        for (int o = 16; o > 0; o >>= 1) se += __shfl_xor_sync(0xffffffffu, se, o);
        if (lane == 0) { sstat[h * 2] = M; sstat[h * 2 + 1] = 1.f / se; }
    }
    __syncthreads();
    float M0 = sstat[0], I0 = sstat[1], M1 = sstat[2], I1 = sstat[3];

    const float* r0 = g_attraw + ((b * 2 + 0) * 32 + x) * 1024;
    const float* r1 = g_attraw + ((b * 2 + 1) * 32 + x) * 1024;
    float* o0 = att_out + ((b * 2 + 0) * 32 + x) * 1024;
    float* o1 = att_out + ((b * 2 + 1) * 32 + x) * 1024;
    #pragma unroll
    for (int i = tid; i < 1024; i += 256) {
        float a0 = expf(r0[i] - M0) * I0;
        float a1 = expf(r1[i] - M1) * I1;
        o0[i] = a0;
        o1[i] = a1;
        sa[i] = a0 + a1;
    }
    __syncthreads();

    float sxk = g_hx[(b * 32 + x) * 256 + tid];
    const float* hyB = g_hy + b * 8192;
    float p = 0.f;
    #pragma unroll
    for (int y0 = 0; y0 < 32; y0 += 4) {
        u64 ps0 = 0, ps1 = 0, ps2 = 0, ps3 = 0;   // f32x2 accumulators over z-pairs
        #pragma unroll
        for (int zc = 0; zc < 8; zc++) {
            // sa quads are 16B aligned: read as b64 halves (z pairs)
            const u64* a0p = (const u64*)&sa[(y0 + 0) * 32 + zc * 4];
            const u64* a1p = (const u64*)&sa[(y0 + 1) * 32 + zc * 4];
            const u64* a2p = (const u64*)&sa[(y0 + 2) * 32 + zc * 4];
            const u64* a3p = (const u64*)&sa[(y0 + 3) * 32 + zc * 4];
            float h0 = shzN[(zc * 4 + 0) * 256 + tid];
            float h1 = shzN[(zc * 4 + 1) * 256 + tid];
            float h2 = shzN[(zc * 4 + 2) * 256 + tid];
            float h3 = shzN[(zc * 4 + 3) * 256 + tid];
            u64 h01, h23;
            PACK2(h01, h0, h1);
            PACK2(h23, h2, h3);
            FFMA2(ps0, a0p[0], h01); FFMA2(ps0, a0p[1], h23);
            FFMA2(ps1, a1p[0], h01); FFMA2(ps1, a1p[1], h23);
            FFMA2(ps2, a2p[0], h01); FFMA2(ps2, a2p[1], h23);
            FFMA2(ps3, a3p[0], h01); FFMA2(ps3, a3p[1], h23);
        }
        float lo, hi, s0, s1, s2, s3;
        UNPACK2(lo, hi, ps0); s0 = lo + hi;
        UNPACK2(lo, hi, ps1); s1 = lo + hi;
        UNPACK2(lo, hi, ps2); s2 = lo + hi;
        UNPACK2(lo, hi, ps3); s3 = lo + hi;
        float t0 = hyB[(y0 + 0) * 256 + tid];
        float t1 = hyB[(y0 + 1) * 256 + tid];
        float t2 = hyB[(y0 + 2) * 256 + tid];
        float t3 = hyB[(y0 + 3) * 256 + tid];
        p += sxk * (t0 * s0 + t1 * s1 + t2 * s2 + t3 * s3);
    }
    g_part[(b * 32 + x) * 256 + tid] = p;
}

// ---------------- K4: reduce partials + BatchNorm (R13-identical) ----------------
__global__ void __launch_bounds__(256) k_bn(const float* __restrict__ gamma,
                                            const float* __restrict__ beta,
                                            float* __restrict__ outp) {
    int warp = threadIdx.x >> 5, lane = threadIdx.x & 31;
    int k = blockIdx.x * 8 + warp;
    float l[8];
    #pragma unroll
    for (int b = 0; b < 8; b++) l[b] = g_part[(b * 32 + lane) * 256 + k];
    #pragma unroll
    for (int b = 0; b < 8; b++) {
        float v = l[b];
        #pragma unroll
        for (int o = 16; o > 0; o >>= 1) v += __shfl_xor_sync(0xffffffffu, v, o);
        l[b] = v;
    }
    float mean = 0.f;
    #pragma unroll
    for (int b = 0; b < 8; b++) mean += l[b];
    mean *= 0.125f;
    float var = 0.f;
    #pragma unroll
    for (int b = 0; b < 8; b++) { float d = l[b] - mean; var += d * d; }
    var *= 0.125f;
    float sc = gamma[k] / sqrtf(var + 1e-5f);
    float bt = beta[k];
    if (lane < 8) outp[lane * 256 + k] = (l[lane] - mean) * sc + bt;
}

// ---------------- launch ----------------
extern "C" void kernel_launch(void* const* d_in, const int* in_sizes, int n_in,
                              void* d_out, int out_size) {
    const float* x     = (const float*)d_in[0];
    const float* y     = (const float*)d_in[1];
    const float* z     = (const float*)d_in[2];
    const float* Vx    = (const float*)d_in[3];
    const float* gx    = (const float*)d_in[4];
    const float* bx    = (const float*)d_in[5];
    const float* Vy    = (const float*)d_in[6];
    const float* gy    = (const float*)d_in[7];
    const float* by    = (const float*)d_in[8];
    const float* Vz    = (const float*)d_in[9];
    const float* gz    = (const float*)d_in[10];
    const float* bz    = (const float*)d_in[11];
    const float* Vh    = (const float*)d_in[12];
    const float* gh    = (const float*)d_in[13];
    const float* bh    = (const float*)d_in[14];
    const float* gamma = (const float*)d_in[15];
    const float* beta  = (const float*)d_in[16];

    float* out     = (float*)d_out;          // [8,256]
    float* att_out = out + 2048;             // [8,2,32,32,32]

    k_proj <<<dim3(4, 8, 3), 256>>>(x, y, z, Vx, gx, bx, Vy, gy, by, Vz, gz, bz);
    k_att  <<<dim3(32, 8), 128>>>(Vh, gh, bh);
    k_fuse <<<dim3(32, 8), 256>>>(att_out);
    k_bn   <<<32, 256>>>(gamma, beta, out);
}

// round 16
// speedup vs baseline: 1.5068x; 1.5068x over previous
#include <cuda_runtime.h>

// ---------------- scratch (__device__ globals; no allocation allowed) ----------------
__device__ float g_hx[8*32*256];
__device__ float g_hy[8*32*256];
__device__ float g_hz[8*32*256];
__device__ float g_attraw[8*2*32768];        // pre-softmax logits [b][h][x][y][z]
__device__ float g_partmax[8*2*32];          // per (b,h,x) block max
__device__ float g_partsum[8*2*32];          // per (b,h,x) Σexp(v - localmax)
__device__ float g_part[8*32*256];           // per (b,x) logits partials

// ---------------- K1: projections (R13-identical + PDL trigger) ----------------
__global__ void __launch_bounds__(256) k_proj(
    const float* __restrict__ xin, const float* __restrict__ yin, const float* __restrict__ zin,
    const float* __restrict__ Vx, const float* __restrict__ gx, const float* __restrict__ bx,
    const float* __restrict__ Vy, const float* __restrict__ gy, const float* __restrict__ by,
    const float* __restrict__ Vz, const float* __restrict__ gz, const float* __restrict__ bz) {
    __shared__ float sIn[32*128];
    __shared__ float sV[64*33];
    __shared__ float red[256];
    int q = blockIdx.x, b = blockIdx.y, m = blockIdx.z;
    const float* in   = (m == 0) ? xin : (m == 1) ? yin : zin;
    const float* V    = (m == 0) ? Vx  : (m == 1) ? Vy  : Vz;
    const float* gp   = (m == 0) ? gx  : (m == 1) ? gy  : gz;
    const float* bias = (m == 0) ? bx  : (m == 1) ? by  : bz;
    float* out        = (m == 0) ? g_hx : (m == 1) ? g_hy : g_hz;
    int tid = threadIdx.x;
    int k0 = q * 64;

    for (int e = tid; e < 4096; e += 256) sIn[e] = in[b * 4096 + e];
    const float4* V4 = (const float4*)V;
    float ss = 0.f;
    #pragma unroll 8
    for (int i = tid; i < 8192; i += 256) {
        float4 v = V4[i];
        ss += v.x*v.x + v.y*v.y + v.z*v.z + v.w*v.w;
    }

    int kk = tid & 63, rg = tid >> 6, r0 = rg * 8;
    float acc[8] = {0,0,0,0,0,0,0,0};
    for (int dc = 0; dc < 128; dc += 32) {
        __syncthreads();
        for (int e = tid; e < 2048; e += 256) {
            int kr = e >> 5, d = e & 31;
            sV[kr * 33 + d] = V[(k0 + kr) * 128 + dc + d];
        }
        __syncthreads();
        for (int d = 0; d < 32; d += 4) {
            float v0 = sV[kk*33 + d],     v1 = sV[kk*33 + d + 1];
            float v2 = sV[kk*33 + d + 2], v3 = sV[kk*33 + d + 3];
            #pragma unroll
            for (int r = 0; r < 8; r++) {
                float4 iv = *(const float4*)&sIn[(r0 + r) * 128 + dc + d];
                acc[r] += iv.x * v0 + iv.y * v1 + iv.z * v2 + iv.w * v3;
            }
        }
    }
    __syncthreads();
    red[tid] = ss; __syncthreads();
    for (int s = 128; s > 0; s >>= 1) {
        if (tid < s) red[tid] += red[tid + s];
        __syncthreads();
    }
    float scale = gp[0] / sqrtf(red[0]);
    float bb = bias[k0 + kk];
    #pragma unroll
    for (int r = 0; r < 8; r++) {
        float v = acc[r] * scale + bb;
        out[(b * 32 + r0 + r) * 256 + k0 + kk] = v > 0.f ? v : 0.f;
    }
    cudaTriggerProgrammaticLaunchCompletion();
}

// ---------------- K2: att GEMM + online-softmax partials (R13-identical + PDL) ----------------
__global__ void __launch_bounds__(128) k_att(const float* __restrict__ Vh,
                                             const float* __restrict__ ghp,
                                             const float* __restrict__ bhp) {
    __shared__ float st[32*64];
    __shared__ float sw[64*68];
    __shared__ float red[128];
    int x = blockIdx.x, b = blockIdx.y;
    int tid = threadIdx.x;
    int yg = tid >> 4, zg = tid & 15;

    // independent pre-work: ||Vh|| from an input tensor (no producer dependency)
    float ssh = 0.f;
    for (int i = tid; i < 512; i += 128) { float v = Vh[i]; ssh += v * v; }
    red[tid] = ssh; __syncthreads();
    for (int s = 64; s > 0; s >>= 1) { if (tid < s) red[tid] += red[tid + s]; __syncthreads(); }
    float scaleH = ghp[0] / sqrtf(red[0]);

    // wait for k_proj's writes (g_hx/g_hy/g_hz) to be visible
    cudaGridDependencySynchronize();

    float4 acc[4];
    acc[0] = acc[1] = acc[2] = acc[3] = make_float4(0.f, 0.f, 0.f, 0.f);
    const float* hx  = g_hx + (b * 32 + x) * 256;
    const float* hyB = g_hy + b * 8192;
    const float* hzB = g_hz + b * 8192;
    for (int c = 0; c < 4; c++) {
        int k0 = c * 64;
        __syncthreads();
        for (int e = tid; e < 2048; e += 128) {
            int kc = e & 63, y = e >> 6;
            st[y * 64 + kc] = hx[k0 + kc] * hyB[y * 256 + k0 + kc];
        }
        for (int e = tid; e < 4096; e += 128) {
            int kc = e & 63, zh = e >> 6;
            sw[kc * 68 + zh] = hzB[(zh >> 1) * 256 + k0 + kc] *
                               Vh[(zh & 1) * 256 + k0 + kc] * scaleH;
        }
        __syncthreads();
        #pragma unroll 4
        for (int kc = 0; kc < 64; kc++) {
            float4 w = *(const float4*)&sw[kc * 68 + zg * 4];
            float t0 = st[(yg*4 + 0) * 64 + kc];
            float t1 = st[(yg*4 + 1) * 64 + kc];
            float t2 = st[(yg*4 + 2) * 64 + kc];
            float t3 = st[(yg*4 + 3) * 64 + kc];
            acc[0].x += t0*w.x; acc[0].y += t0*w.y; acc[0].z += t0*w.z; acc[0].w += t0*w.w;
            acc[1].x += t1*w.x; acc[1].y += t1*w.y; acc[1].z += t1*w.z; acc[1].w += t1*w.w;
            acc[2].x += t2*w.x; acc[2].y += t2*w.y; acc[2].z += t2*w.z; acc[2].w += t2*w.w;
            acc[3].x += t3*w.x; acc[3].y += t3*w.y; acc[3].z += t3*w.z; acc[3].w += t3*w.w;
        }
    }
    float b0 = bhp[0], b1 = bhp[1];
    float m0 = -1e30f, m1 = -1e30f;
    float* r0base = g_attraw + ((b * 2 + 0) * 32 + x) * 1024;
    float* r1base = g_attraw + ((b * 2 + 1) * 32 + x) * 1024;
    int z0 = zg * 2;
    #pragma unroll
    for (int i = 0; i < 4; i++) {
        int y = yg * 4 + i;
        float4 v = acc[i];
        v.x += b0; v.y += b1; v.z += b0; v.w += b1;
        m0 = fmaxf(m0, fmaxf(v.x, v.z));
        m1 = fmaxf(m1, fmaxf(v.y, v.w));
        r0base[y * 32 + z0]     = v.x;
        r1base[y * 32 + z0]     = v.y;
        r0base[y * 32 + z0 + 1] = v.z;
        r1base[y * 32 + z0 + 1] = v.w;
    }
    __syncthreads();
    red[tid] = m0; __syncthreads();
    for (int s = 64; s > 0; s >>= 1) { if (tid < s) red[tid] = fmaxf(red[tid], red[tid + s]); __syncthreads(); }
    float M0 = red[0]; __syncthreads();
    red[tid] = m1; __syncthreads();
    for (int s = 64; s > 0; s >>= 1) { if (tid < s) red[tid] = fmaxf(red[tid], red[tid + s]); __syncthreads(); }
    float M1 = red[0]; __syncthreads();
    float s0 = 0.f, s1 = 0.f;
    #pragma unroll
    for (int i = 0; i < 4; i++) {
        float4 v = acc[i];
        s0 += expf(v.x + b0 - M0) + expf(v.z + b0 - M0);
        s1 += expf(v.y + b1 - M1) + expf(v.w + b1 - M1);
    }
    red[tid] = s0; __syncthreads();
    for (int s = 64; s > 0; s >>= 1) { if (tid < s) red[tid] += red[tid + s]; __syncthreads(); }
    float S0 = red[0]; __syncthreads();
    red[tid] = s1; __syncthreads();
    for (int s = 64; s > 0; s >>= 1) { if (tid < s) red[tid] += red[tid + s]; __syncthreads(); }
    if (tid == 0) {
        g_partmax[(b * 2 + 0) * 32 + x] = M0;
        g_partmax[(b * 2 + 1) * 32 + x] = M1;
        g_partsum[(b * 2 + 0) * 32 + x] = S0;
        g_partsum[(b * 2 + 1) * 32 + x] = red[0];
    }
    cudaTriggerProgrammaticLaunchCompletion();
}

// ---------------- K3: softmax-finalize + att_out + logit partials (R13-identical + PDL) ----------------
__global__ void __launch_bounds__(256) k_fuse(float* __restrict__ att_out) {
    __shared__ float sa[1024];
    __shared__ float shzN[8192];   // [z][k], natural
    __shared__ float sstat[4];
    int x = blockIdx.x, b = blockIdx.y, tid = threadIdx.x;

    // independent pre-work: stage g_hz — produced by k_proj, which completed before
    // k_att (our PDL predecessor) began its post-sync phase; safe pre-sync.
    const float* hzB = g_hz + b * 8192;
    {
        float4* s4 = (float4*)shzN;
        const float4* g4 = (const float4*)hzB;
        for (int e = tid; e < 2048; e += 256) s4[e] = g4[e];
    }

    // wait for k_att's writes (g_attraw / g_partmax / g_partsum)
    cudaGridDependencySynchronize();

    if (tid < 64) {
        int h = tid >> 5, lane = tid & 31;
        float m = g_partmax[(b * 2 + h) * 32 + lane];
        float s = g_partsum[(b * 2 + h) * 32 + lane];
        float M = m;
        #pragma unroll
        for (int o = 16; o > 0; o >>= 1) M = fmaxf(M, __shfl_xor_sync(0xffffffffu, M, o));
        float se = s * expf(m - M);
        #pragma unroll
        for (int o = 16; o > 0; o >>= 1) se += __shfl_xor_sync(0xffffffffu, se, o);
        if (lane == 0) { sstat[h * 2] = M; sstat[h * 2 + 1] = 1.f / se; }
    }
    __syncthreads();
    float M0 = sstat[0], I0 = sstat[1], M1 = sstat[2], I1 = sstat[3];

    const float* r0 = g_attraw + ((b * 2 + 0) * 32 + x) * 1024;
    const float* r1 = g_attraw + ((b * 2 + 1) * 32 + x) * 1024;
    float* o0 = att_out + ((b * 2 + 0) * 32 + x) * 1024;
    float* o1 = att_out + ((b * 2 + 1) * 32 + x) * 1024;
    #pragma unroll
    for (int i = tid; i < 1024; i += 256) {
        float a0 = expf(r0[i] - M0) * I0;
        float a1 = expf(r1[i] - M1) * I1;
        o0[i] = a0;
        o1[i] = a1;
        sa[i] = a0 + a1;
    }
    __syncthreads();

    float sxk = g_hx[(b * 32 + x) * 256 + tid];
    const float* hyB = g_hy + b * 8192;
    const float4* sa4 = (const float4*)sa;
    float p = 0.f;
    #pragma unroll
    for (int y0 = 0; y0 < 32; y0 += 4) {
        float s0 = 0.f, s1 = 0.f, s2 = 0.f, s3 = 0.f;
        #pragma unroll
        for (int zc = 0; zc < 8; zc++) {
            float4 a0 = sa4[(y0 + 0) * 8 + zc];
            float4 a1 = sa4[(y0 + 1) * 8 + zc];
            float4 a2 = sa4[(y0 + 2) * 8 + zc];
            float4 a3 = sa4[(y0 + 3) * 8 + zc];
            float h0 = shzN[(zc * 4 + 0) * 256 + tid];
            float h1 = shzN[(zc * 4 + 1) * 256 + tid];
            float h2 = shzN[(zc * 4 + 2) * 256 + tid];
            float h3 = shzN[(zc * 4 + 3) * 256 + tid];
            s0 += a0.x*h0 + a0.y*h1 + a0.z*h2 + a0.w*h3;
            s1 += a1.x*h0 + a1.y*h1 + a1.z*h2 + a1.w*h3;
            s2 += a2.x*h0 + a2.y*h1 + a2.z*h2 + a2.w*h3;
            s3 += a3.x*h0 + a3.y*h1 + a3.z*h2 + a3.w*h3;
        }
        float t0 = hyB[(y0 + 0) * 256 + tid];
        float t1 = hyB[(y0 + 1) * 256 + tid];
        float t2 = hyB[(y0 + 2) * 256 + tid];
        float t3 = hyB[(y0 + 3) * 256 + tid];
        p += sxk * (t0 * s0 + t1 * s1 + t2 * s2 + t3 * s3);
    }
    g_part[(b * 32 + x) * 256 + tid] = p;
    cudaTriggerProgrammaticLaunchCompletion();
}

// ---------------- K4: reduce partials + BatchNorm (R13-identical + PDL sync) ----------------
__global__ void __launch_bounds__(256) k_bn(const float* __restrict__ gamma,
                                            const float* __restrict__ beta,
                                            float* __restrict__ outp) {
    cudaGridDependencySynchronize();
    int warp = threadIdx.x >> 5, lane = threadIdx.x & 31;
    int k = blockIdx.x * 8 + warp;
    float l[8];
    #pragma unroll
    for (int b = 0; b < 8; b++) l[b] = g_part[(b * 32 + lane) * 256 + k];
    #pragma unroll
    for (int b = 0; b < 8; b++) {
        float v = l[b];
        #pragma unroll
        for (int o = 16; o > 0; o >>= 1) v += __shfl_xor_sync(0xffffffffu, v, o);
        l[b] = v;
    }
    float mean = 0.f;
    #pragma unroll
    for (int b = 0; b < 8; b++) mean += l[b];
    mean *= 0.125f;
    float var = 0.f;
    #pragma unroll
    for (int b = 0; b < 8; b++) { float d = l[b] - mean; var += d * d; }
    var *= 0.125f;
    float sc = gamma[k] / sqrtf(var + 1e-5f);
    float bt = beta[k];
    if (lane < 8) outp[lane * 256 + k] = (l[lane] - mean) * sc + bt;
}

// ---------------- launch (PDL chain) ----------------
extern "C" void kernel_launch(void* const* d_in, const int* in_sizes, int n_in,
                              void* d_out, int out_size) {
    const float* x     = (const float*)d_in[0];
    const float* y     = (const float*)d_in[1];
    const float* z     = (const float*)d_in[2];
    const float* Vx    = (const float*)d_in[3];
    const float* gx    = (const float*)d_in[4];
    const float* bx    = (const float*)d_in[5];
    const float* Vy    = (const float*)d_in[6];
    const float* gy    = (const float*)d_in[7];
    const float* by    = (const float*)d_in[8];
    const float* Vz    = (const float*)d_in[9];
    const float* gz    = (const float*)d_in[10];
    const float* bz    = (const float*)d_in[11];
    const float* Vh    = (const float*)d_in[12];
    const float* gh    = (const float*)d_in[13];
    const float* bh    = (const float*)d_in[14];
    const float* gamma = (const float*)d_in[15];
    const float* beta  = (const float*)d_in[16];

    float* out     = (float*)d_out;          // [8,256]
    float* att_out = out + 2048;             // [8,2,32,32,32]

    k_proj<<<dim3(4, 8, 3), 256>>>(x, y, z, Vx, gx, bx, Vy, gy, by, Vz, gz, bz);

    cudaLaunchAttribute attr[1];
    attr[0].id = cudaLaunchAttributeProgrammaticStreamSerialization;
    attr[0].val.programmaticStreamSerializationAllowed = 1;

    {   // k_att
        cudaLaunchConfig_t cfg = {};
        cfg.gridDim = dim3(32, 8); cfg.blockDim = dim3(128);
        cfg.stream = 0; cfg.attrs = attr; cfg.numAttrs = 1;
        cudaLaunchKernelEx(&cfg, k_att, Vh, gh, bh);
    }
    {   // k_fuse
        cudaLaunchConfig_t cfg = {};
        cfg.gridDim = dim3(32, 8); cfg.blockDim = dim3(256);
        cfg.stream = 0; cfg.attrs = attr; cfg.numAttrs = 1;
        cudaLaunchKernelEx(&cfg, k_fuse, att_out);
    }
    {   // k_bn
        cudaLaunchConfig_t cfg = {};
        cfg.gridDim = dim3(32); cfg.blockDim = dim3(256);
        cfg.stream = 0; cfg.attrs = attr; cfg.numAttrs = 1;
        cudaLaunchKernelEx(&cfg, k_bn, gamma, beta, out);
    }
}